// round 12
// baseline (speedup 1.0000x reference)
#include <cuda_runtime.h>
#include <math.h>
#include <stdint.h>

#define N_PTS 131072
#define C 128
#define KNUM 27
#define M_MAP 65536
#define EPS 1e-5f

#define BT 128            // map rows per CTA tile
#define KC 32             // k-elems per chunk
#define NCHUNK (C / KC)   // 4
#define PBQ 48            // int8 smem row pitch (32 valid + 16 pad) — LDSM conflict-free
#define ARRQ (BT * PBQ)   // 6144 B per operand array per chunk
#define A_ST (2 * ARRQ)   // qh+ql = 12288
#define B_ST (2 * ARRQ)
#define BREGQ (3 * A_ST)  // B region after 3 A stages = 36864
#define DYNQ (BREGQ + 2 * B_ST)   // 61440
#define WCH ARRQ          // weight chunk image bytes per array

// ---- scratch (static device allocations; allowed) ----
__device__ __align__(16) float  g_acc[(size_t)N_PTS * C];
__device__ __align__(16) int8_t g_qxh[(size_t)N_PTS * C];
__device__ __align__(16) int8_t g_qxl[(size_t)N_PTS * C];
__device__ __align__(16) int8_t g_qyh[(size_t)N_PTS * C];
__device__ __align__(16) int8_t g_qyl[(size_t)N_PTS * C];
__device__ __align__(16) float  g_sx[N_PTS];
__device__ __align__(16) float  g_sy[N_PTS];
// weight smem-image: [k][chunk][n 0..127][48 B (32 valid int8 cin)]
__device__ __align__(16) int8_t g_wqh[(size_t)KNUM * NCHUNK * ARRQ];
__device__ __align__(16) int8_t g_wql[(size_t)KNUM * NCHUNK * ARRQ];
__device__ __align__(16) float  g_sw[KNUM * C];
__device__ __align__(16) float  g_sum[C];
__device__ __align__(16) float  g_sq[C];
__device__ __align__(16) float  g_scale[C];
__device__ __align__(16) float  g_shift[C];

// ---------------------------------------------------------------------------
// helpers
// ---------------------------------------------------------------------------
__device__ __forceinline__ uint32_t smem_u32(const void* p)
{
    uint32_t a;
    asm("{ .reg .u64 t; cvta.to.shared.u64 t, %1; cvt.u32.u64 %0, t; }"
        : "=r"(a) : "l"(p));
    return a;
}

__device__ __forceinline__ void imma16832(int* c, const unsigned* a,
                                          unsigned b0, unsigned b1)
{
    asm volatile(
        "mma.sync.aligned.m16n8k32.row.col.s32.s8.s8.s32 "
        "{%0,%1,%2,%3}, {%4,%5,%6,%7}, {%8,%9}, {%0,%1,%2,%3};"
        : "+r"(c[0]), "+r"(c[1]), "+r"(c[2]), "+r"(c[3])
        : "r"(a[0]), "r"(a[1]), "r"(a[2]), "r"(a[3]), "r"(b0), "r"(b1));
}

__device__ __forceinline__ void ldsm_x4(unsigned* r, uint32_t addr)
{
    asm volatile("ldmatrix.sync.aligned.m8n8.x4.shared.b16 {%0,%1,%2,%3}, [%4];"
                 : "=r"(r[0]), "=r"(r[1]), "=r"(r[2]), "=r"(r[3]) : "r"(addr));
}

#define CP_ASYNC16(dst, src) \
    asm volatile("cp.async.cg.shared.global [%0], [%1], 16;" :: "r"(dst), "l"(src))
#define CP_COMMIT() asm volatile("cp.async.commit_group;" ::: "memory")

__device__ __forceinline__ void bulk_copy(uint32_t dst, const void* src,
                                          uint32_t bytes, uint32_t mbar)
{
    asm volatile(
        "cp.async.bulk.shared::cta.global.mbarrier::complete_tx::bytes "
        "[%0], [%1], %2, [%3];"
        :: "r"(dst), "l"(src), "r"(bytes), "r"(mbar) : "memory");
}

__device__ __forceinline__ void mbar_expect_tx(uint32_t mbar, uint32_t bytes)
{
    asm volatile("mbarrier.arrive.expect_tx.shared.b64 _, [%0], %1;"
                 :: "r"(mbar), "r"(bytes) : "memory");
}

__device__ __forceinline__ void mbar_wait(uint32_t mbar, uint32_t parity)
{
    uint32_t done;
    asm volatile(
        "{\n\t.reg .pred p;\n\t"
        "mbarrier.try_wait.parity.acquire.cta.shared::cta.b64 p, [%1], %2;\n\t"
        "selp.b32 %0, 1, 0, p;\n\t}"
        : "=r"(done) : "r"(mbar), "r"(parity) : "memory");
    if (!done) {
        asm volatile(
            "{\n\t.reg .pred P1;\n\t"
            "WL_%=:\n\t"
            "mbarrier.try_wait.parity.acquire.cta.shared::cta.b64 P1, [%0], %1, 0x989680;\n\t"
            "@P1 bra.uni WD_%=;\n\t"
            "bra.uni WL_%=;\n\t"
            "WD_%=:\n\t}"
            :: "r"(mbar), "r"(parity) : "memory");
    }
}

// 14-bit quantize + limb split: q in [-8191, 8191]; qh,ql in [-64,64]
__device__ __forceinline__ void q14(float v, float rs, int& qh, int& ql)
{
    int q = __float2int_rn(v * rs);
    qh = (q + 64) >> 7;
    ql = q - (qh << 7);
}

__device__ __forceinline__ unsigned pack4(int a, int b, int c, int d)
{
    return (unsigned)(a & 255) | ((unsigned)(b & 255) << 8)
         | ((unsigned)(c & 255) << 16) | ((unsigned)(d & 255) << 24);
}

__device__ __forceinline__ float elu_f(float x)
{
    return x > 0.0f ? x : expm1f(x);
}

// ---------------------------------------------------------------------------
// quantize x: warp per row; also zeroes acc and (block 0) stats
// ---------------------------------------------------------------------------
__global__ __launch_bounds__(256)
void quant_x_kernel(const float* __restrict__ src)
{
    const int warp = threadIdx.x >> 5;
    const int lane = threadIdx.x & 31;
    const int row  = blockIdx.x * 8 + warp;
    if (blockIdx.x == 0 && threadIdx.x < C) {
        g_sum[threadIdx.x] = 0.0f;
        g_sq[threadIdx.x]  = 0.0f;
    }
    float4 v = ((const float4*)src)[(size_t)row * 32 + lane];
    float m = fmaxf(fmaxf(fabsf(v.x), fabsf(v.y)), fmaxf(fabsf(v.z), fabsf(v.w)));
    #pragma unroll
    for (int off = 16; off; off >>= 1)
        m = fmaxf(m, __shfl_xor_sync(0xFFFFFFFFu, m, off));
    float rs = m > 0.f ? 8191.0f / m : 0.0f;
    int h0, l0, h1, l1, h2, l2, h3, l3;
    q14(v.x, rs, h0, l0); q14(v.y, rs, h1, l1);
    q14(v.z, rs, h2, l2); q14(v.w, rs, h3, l3);
    ((unsigned*)g_qxh)[(size_t)row * 32 + lane] = pack4(h0, h1, h2, h3);
    ((unsigned*)g_qxl)[(size_t)row * 32 + lane] = pack4(l0, l1, l2, l3);
    if (lane == 0) g_sx[row] = m * (1.0f / 8191.0f);
    ((float4*)g_acc)[(size_t)row * 32 + lane] = make_float4(0.f, 0.f, 0.f, 0.f);
}

// ---------------------------------------------------------------------------
// quantize W[k]: per-column max over cin, then split-limb into smem-image
// ---------------------------------------------------------------------------
__global__ __launch_bounds__(256)
void quant_w_kernel(const float* __restrict__ W)
{
    __shared__ float rsw[C];
    const int k = blockIdx.x;
    const float* Wk = W + (size_t)k * C * C;
    const int tid = threadIdx.x;
    if (tid < C) {
        float m = 0.f;
        for (int cin = 0; cin < C; cin++)
            m = fmaxf(m, fabsf(Wk[(size_t)cin * C + tid]));
        g_sw[k * C + tid] = m * (1.0f / 8191.0f);
        rsw[tid] = m > 0.f ? 8191.0f / m : 0.0f;
    }
    __syncthreads();
    for (int idx = tid; idx < C * C; idx += 256) {
        int n   = idx & (C - 1);
        int cin = idx >> 7;
        int qh, ql;
        q14(Wk[(size_t)cin * C + n], rsw[n], qh, ql);
        size_t off = ((size_t)(k * NCHUNK + (cin >> 5)) * BT + n) * PBQ + (cin & 31);
        g_wqh[off] = (int8_t)qh;
        g_wql[off] = (int8_t)ql;
    }
}

// ---------------------------------------------------------------------------
// Sparse conv, int8 limbs: 512 threads, 16 warps, warp tile 32M x 32N.
// A via 3-stage cp.async gather; B via 2-stage cp.async.bulk.
// D = Sx*Sw*(16384*Shh + 128*Scross); scatter via red.global.v4.f32.
// ---------------------------------------------------------------------------
__global__ __launch_bounds__(512, 1)
void spconv_s8_kernel(const int8_t* __restrict__ qxh,
                      const int8_t* __restrict__ qxl,
                      const float* __restrict__ sxp,
                      const int* __restrict__ map_in,
                      const int* __restrict__ map_out,
                      float* __restrict__ acc_out)
{
    extern __shared__ __align__(16) char dynsmem[];
    __shared__ int   rowidx[BT];
    __shared__ float sxs[BT];
    __shared__ float sws[C];
    __shared__ __align__(8) uint64_t s_mbar[2];

    const int k    = blockIdx.y;
    const int m0   = blockIdx.x * BT;
    const int tid  = threadIdx.x;
    const int warp = tid >> 5;
    const int lane = tid & 31;
    const int wm   = warp & 3;            // M warp: 32 rows
    const int wn   = warp >> 2;           // N warp: 32 cols

    const int* mi = map_in  + (size_t)k * M_MAP + m0;
    const int* mo = map_out + (size_t)k * M_MAP + m0;
    const char* wbh = (const char*)g_wqh + (size_t)k * NCHUNK * WCH;
    const char* wbl = (const char*)g_wql + (size_t)k * NCHUNK * WCH;

    const uint32_t sbase = smem_u32(dynsmem);
    const uint32_t mb0   = smem_u32(&s_mbar[0]);
    const uint32_t mb1   = smem_u32(&s_mbar[1]);

    if (tid < BT) rowidx[tid] = mi[tid];
    if (tid >= 256 && tid < 256 + C) sws[tid - 256] = g_sw[k * C + (tid - 256)];
    if (tid == 0) {
        asm volatile("mbarrier.init.shared.b64 [%0], 1;" :: "r"(mb0) : "memory");
        asm volatile("mbarrier.init.shared.b64 [%0], 1;" :: "r"(mb1) : "memory");
        asm volatile("fence.proxy.async.shared::cta;" ::: "memory");
    }
    __syncthreads();
    if (tid < BT) sxs[tid] = sxp[rowidx[tid]];

    // --- per-thread cp.async A transfer (1 per chunk) ---
    const int arr = tid >> 8;             // 0: qh, 1: ql
    const int rem = tid & 255;
    const int arow = rem >> 1;
    const int agr  = rem & 1;
    const int8_t* asrc = (arr ? qxl : qxh) + (size_t)rowidx[arow] * C + agr * 16;
    const uint32_t adoff = (uint32_t)(arr * ARRQ + arow * PBQ + agr * 16);

    // --- ldmatrix offsets (bytes within a stage) ---
    const int mat = lane >> 3;
    const int mi8 = lane & 7;
    uint32_t aOffQ[2];
    #pragma unroll
    for (int mb = 0; mb < 2; mb++)
        aOffQ[mb] = (uint32_t)((wm * 32 + mb * 16 + (mat & 1) * 8 + mi8) * PBQ
                               + (mat >> 1) * 16);
    uint32_t bOffQ[2];
    #pragma unroll
    for (int p = 0; p < 2; p++)
        bOffQ[p] = (uint32_t)((wn * 32 + p * 16 + (mat & 1) * 8 + mi8) * PBQ
                              + (mat >> 1) * 16);

    int shh[2][4][4], scr[2][4][4];
    #pragma unroll
    for (int i = 0; i < 2; i++)
        #pragma unroll
        for (int j = 0; j < 4; j++)
            #pragma unroll
            for (int t = 0; t < 4; t++) { shh[i][j][t] = 0; scr[i][j][t] = 0; }

    // ---- preload A chunks 0,1 and B chunk 0 ----
    #pragma unroll
    for (int pre = 0; pre < 2; pre++) {
        CP_ASYNC16(sbase + pre * A_ST + adoff, asrc + pre * KC);
        CP_COMMIT();
    }
    if (tid == 0) {
        mbar_expect_tx(mb0, 2 * WCH);
        bulk_copy(sbase + BREGQ, wbh, WCH, mb0);
        bulk_copy(sbase + BREGQ + ARRQ, wbl, WCH, mb0);
    }

    #pragma unroll
    for (int ch = 0; ch < NCHUNK; ch++) {
        if (ch < NCHUNK - 1) asm volatile("cp.async.wait_group 1;" ::: "memory");
        else                 asm volatile("cp.async.wait_group 0;" ::: "memory");
        mbar_wait((ch & 1) ? mb1 : mb0, (uint32_t)((ch >> 1) & 1));
        __syncthreads();

        if (ch + 2 < NCHUNK) {
            CP_ASYNC16(sbase + ((ch + 2) % 3) * A_ST + adoff, asrc + (ch + 2) * KC);
            CP_COMMIT();
        }
        if (ch + 1 < NCHUNK && tid == 0) {
            const uint32_t nmb = ((ch + 1) & 1) ? mb1 : mb0;
            const uint32_t dst = sbase + BREGQ + (uint32_t)(((ch + 1) & 1) * B_ST);
            mbar_expect_tx(nmb, 2 * WCH);
            bulk_copy(dst, wbh + (size_t)(ch + 1) * WCH, WCH, nmb);
            bulk_copy(dst + ARRQ, wbl + (size_t)(ch + 1) * WCH, WCH, nmb);
        }

        const uint32_t stA = sbase + (uint32_t)((ch % 3) * A_ST);
        const uint32_t stB = sbase + BREGQ + (uint32_t)((ch % 2) * B_ST);

        unsigned ah[2][4], al[2][4];
        #pragma unroll
        for (int mb = 0; mb < 2; mb++) {
            ldsm_x4(ah[mb], stA + aOffQ[mb]);
            ldsm_x4(al[mb], stA + ARRQ + aOffQ[mb]);
        }
        #pragma unroll
        for (int p = 0; p < 2; p++) {
            unsigned bh[4], bl[4];
            ldsm_x4(bh, stB + bOffQ[p]);
            ldsm_x4(bl, stB + ARRQ + bOffQ[p]);
            #pragma unroll
            for (int ns = 0; ns < 2; ns++) {
                const int nb = p * 2 + ns;
                const unsigned b0h = bh[ns], b1h = bh[ns + 2];
                const unsigned b0l = bl[ns], b1l = bl[ns + 2];
                #pragma unroll
                for (int mb = 0; mb < 2; mb++) {
                    imma16832(shh[mb][nb], ah[mb], b0h, b1h);
                    imma16832(scr[mb][nb], ah[mb], b0l, b1l);
                    imma16832(scr[mb][nb], al[mb], b0h, b1h);
                }
            }
        }
        if (ch < NCHUNK - 1) __syncthreads();
    }

    // ---- epilogue: dequant, shfl-swap into 4-col runs, scatter v4 reds ----
    {
        const int g    = lane >> 2;
        const int tig  = lane & 3;
        const int oddp = tig & 1;
        const int cbase = wn * 32 + (tig >> 1) * 4;
        #pragma unroll
        for (int mb = 0; mb < 2; mb++) {
            const int r    = wm * 32 + mb * 16 + g + oddp * 8;
            const int orow = mo[r];
            const float sxr = sxs[r];
            float* dst = acc_out + (size_t)orow * C + cbase;
            #pragma unroll
            for (int nb = 0; nb < 4; nb++) {
                float f0 = fmaf(16384.f, (float)shh[mb][nb][0], 128.f * (float)scr[mb][nb][0]);
                float f1 = fmaf(16384.f, (float)shh[mb][nb][1], 128.f * (float)scr[mb][nb][1]);
                float f2 = fmaf(16384.f, (float)shh[mb][nb][2], 128.f * (float)scr[mb][nb][2]);
                float f3 = fmaf(16384.f, (float)shh[mb][nb][3], 128.f * (float)scr[mb][nb][3]);
                float s0 = oddp ? f0 : f2;
                float s1 = oddp ? f1 : f3;
                float r0 = __shfl_xor_sync(0xFFFFFFFFu, s0, 1);
                float r1 = __shfl_xor_sync(0xFFFFFFFFu, s1, 1);
                float v0 = oddp ? r0 : f0;
                float v1 = oddp ? r1 : f1;
                float v2 = oddp ? f2 : r0;
                float v3 = oddp ? f3 : r1;
                float4 sw4 = *(const float4*)&sws[cbase + nb * 8];
                v0 *= sxr * sw4.x;
                v1 *= sxr * sw4.y;
                v2 *= sxr * sw4.z;
                v3 *= sxr * sw4.w;
                asm volatile("red.global.v4.f32.add [%0], {%1, %2, %3, %4};"
                             :: "l"(dst + nb * 8), "f"(v0), "f"(v1), "f"(v2), "f"(v3)
                             : "memory");
            }
        }
    }
}

// ---------------------------------------------------------------------------
// BN stats / finalize
// ---------------------------------------------------------------------------
__global__ __launch_bounds__(256)
void bn_stats_kernel(const float* __restrict__ a)
{
    __shared__ float4 ss[256];
    __shared__ float4 qq[256];
    const int tid = threadIdx.x;
    const int c4  = tid & 31;
    const int ro  = tid >> 5;

    float4 s = make_float4(0.f, 0.f, 0.f, 0.f);
    float4 p = make_float4(0.f, 0.f, 0.f, 0.f);
    for (int r = blockIdx.x * 8 + ro; r < N_PTS; r += gridDim.x * 8) {
        float4 v = ((const float4*)a)[(size_t)r * 32 + c4];
        s.x += v.x; s.y += v.y; s.z += v.z; s.w += v.w;
        p.x += v.x * v.x; p.y += v.y * v.y; p.z += v.z * v.z; p.w += v.w * v.w;
    }
    ss[tid] = s;
    qq[tid] = p;
    __syncthreads();
    if (tid < 32) {
        float4 S = ss[tid], Q = qq[tid];
        #pragma unroll
        for (int j = 1; j < 8; j++) {
            float4 s2 = ss[tid + j * 32], q2 = qq[tid + j * 32];
            S.x += s2.x; S.y += s2.y; S.z += s2.z; S.w += s2.w;
            Q.x += q2.x; Q.y += q2.y; Q.z += q2.z; Q.w += q2.w;
        }
        atomicAdd(&g_sum[tid * 4 + 0], S.x);
        atomicAdd(&g_sum[tid * 4 + 1], S.y);
        atomicAdd(&g_sum[tid * 4 + 2], S.z);
        atomicAdd(&g_sum[tid * 4 + 3], S.w);
        atomicAdd(&g_sq[tid * 4 + 0], Q.x);
        atomicAdd(&g_sq[tid * 4 + 1], Q.y);
        atomicAdd(&g_sq[tid * 4 + 2], Q.z);
        atomicAdd(&g_sq[tid * 4 + 3], Q.w);
    }
}

__global__ void bn_finalize_kernel(const float* __restrict__ gamma,
                                   const float* __restrict__ beta)
{
    int c = threadIdx.x;
    float m  = g_sum[c] * (1.0f / N_PTS);
    float v  = g_sq[c] * (1.0f / N_PTS) - m * m;
    float is = rsqrtf(v + EPS);
    float sc = is * gamma[c];
    g_scale[c] = sc;
    g_shift[c] = beta[c] - m * sc;
}

// ---------------------------------------------------------------------------
// BN + ELU -> quantized y (warp per row); zeroes acc + stats for layer 2
// ---------------------------------------------------------------------------
__global__ __launch_bounds__(256)
void apply_bn_elu_quant_kernel(float* __restrict__ a)
{
    const int warp = threadIdx.x >> 5;
    const int lane = threadIdx.x & 31;
    const int row  = blockIdx.x * 8 + warp;
    if (blockIdx.x == 0 && threadIdx.x < C) {
        g_sum[threadIdx.x] = 0.0f;
        g_sq[threadIdx.x]  = 0.0f;
    }
    float4 v  = ((const float4*)a)[(size_t)row * 32 + lane];
    float4 sc = ((const float4*)g_scale)[lane];
    float4 sh = ((const float4*)g_shift)[lane];
    float4 y;
    y.x = elu_f(fmaf(v.x, sc.x, sh.x));
    y.y = elu_f(fmaf(v.y, sc.y, sh.y));
    y.z = elu_f(fmaf(v.z, sc.z, sh.z));
    y.w = elu_f(fmaf(v.w, sc.w, sh.w));
    ((float4*)a)[(size_t)row * 32 + lane] = make_float4(0.f, 0.f, 0.f, 0.f);

    float m = fmaxf(fmaxf(fabsf(y.x), fabsf(y.y)), fmaxf(fabsf(y.z), fabsf(y.w)));
    #pragma unroll
    for (int off = 16; off; off >>= 1)
        m = fmaxf(m, __shfl_xor_sync(0xFFFFFFFFu, m, off));
    float rs = m > 0.f ? 8191.0f / m : 0.0f;
    int h0, l0, h1, l1, h2, l2, h3, l3;
    q14(y.x, rs, h0, l0); q14(y.y, rs, h1, l1);
    q14(y.z, rs, h2, l2); q14(y.w, rs, h3, l3);
    ((unsigned*)g_qyh)[(size_t)row * 32 + lane] = pack4(h0, h1, h2, h3);
    ((unsigned*)g_qyl)[(size_t)row * 32 + lane] = pack4(l0, l1, l2, l3);
    if (lane == 0) g_sy[row] = m * (1.0f / 8191.0f);
}

// ---------------------------------------------------------------------------
// final: BN + residual + ELU
// ---------------------------------------------------------------------------
__global__ __launch_bounds__(256)
void apply_bn_res_elu_kernel(const float* __restrict__ a,
                             const float* __restrict__ resid,
                             float* __restrict__ o)
{
    size_t idx = (size_t)blockIdx.x * 256 + threadIdx.x;
    int c4 = (int)(idx & 31);
    float4 v  = ((const float4*)a)[idx];
    float4 rs = ((const float4*)resid)[idx];
    float4 sc = ((const float4*)g_scale)[c4];
    float4 sh = ((const float4*)g_shift)[c4];
    float4 r;
    r.x = elu_f(fmaf(v.x, sc.x, sh.x) + rs.x);
    r.y = elu_f(fmaf(v.y, sc.y, sh.y) + rs.y);
    r.z = elu_f(fmaf(v.z, sc.z, sh.z) + rs.z);
    r.w = elu_f(fmaf(v.w, sc.w, sh.w) + rs.w);
    ((float4*)o)[idx] = r;
}

// ---------------------------------------------------------------------------
// Launch
// ---------------------------------------------------------------------------
extern "C" void kernel_launch(void* const* d_in, const int* in_sizes, int n_in,
                              void* d_out, int out_size)
{
    const float* x       = (const float*)d_in[0];
    const float* W1      = (const float*)d_in[1];
    const float* gamma1  = (const float*)d_in[2];
    const float* beta1   = (const float*)d_in[3];
    const float* W2      = (const float*)d_in[4];
    const float* gamma2  = (const float*)d_in[5];
    const float* beta2   = (const float*)d_in[6];
    const int*   map1_in  = (const int*)d_in[7];
    const int*   map1_out = (const int*)d_in[8];
    const int*   map2_in  = (const int*)d_in[9];
    const int*   map2_out = (const int*)d_in[10];
    float* out = (float*)d_out;

    void *accPtr, *qxhPtr, *qxlPtr, *qyhPtr, *qylPtr, *sxPtr, *syPtr;
    cudaGetSymbolAddress(&accPtr, g_acc);
    cudaGetSymbolAddress(&qxhPtr, g_qxh);
    cudaGetSymbolAddress(&qxlPtr, g_qxl);
    cudaGetSymbolAddress(&qyhPtr, g_qyh);
    cudaGetSymbolAddress(&qylPtr, g_qyl);
    cudaGetSymbolAddress(&sxPtr, g_sx);
    cudaGetSymbolAddress(&syPtr, g_sy);

    cudaFuncSetAttribute(spconv_s8_kernel,
                         cudaFuncAttributeMaxDynamicSharedMemorySize, DYNQ);

    const dim3 convGrid(M_MAP / BT, KNUM);
    const int  rowGrid = N_PTS / 8;                // warp-per-row kernels
    const int  ewGrid  = (N_PTS * C) / 4 / 256;

    // ---- quantize inputs (also zeroes acc + stats) ----
    quant_x_kernel<<<rowGrid, 256>>>(x);
    quant_w_kernel<<<KNUM, 256>>>(W1);

    // ---- layer 1 ----
    spconv_s8_kernel<<<convGrid, 512, DYNQ>>>(
        (const int8_t*)qxhPtr, (const int8_t*)qxlPtr, (const float*)sxPtr,
        map1_in, map1_out, (float*)accPtr);
    bn_stats_kernel<<<1024, 256>>>((const float*)accPtr);
    bn_finalize_kernel<<<1, C>>>(gamma1, beta1);
    apply_bn_elu_quant_kernel<<<rowGrid, 256>>>((float*)accPtr);

    // ---- layer 2 ----
    quant_w_kernel<<<KNUM, 256>>>(W2);
    spconv_s8_kernel<<<convGrid, 512, DYNQ>>>(
        (const int8_t*)qyhPtr, (const int8_t*)qylPtr, (const float*)syPtr,
        map2_in, map2_out, (float*)accPtr);
    bn_stats_kernel<<<1024, 256>>>((const float*)accPtr);
    bn_finalize_kernel<<<1, C>>>(gamma2, beta2);
    apply_bn_res_elu_kernel<<<ewGrid, 256>>>((const float*)accPtr, x, out);
}

// round 14
// speedup vs baseline: 2.4883x; 2.4883x over previous
#include <cuda_runtime.h>
#include <cuda_bf16.h>
#include <math.h>
#include <stdint.h>

#define N_PTS 131072
#define C 128
#define KNUM 27
#define M_MAP 65536
#define EPS 1e-5f

#define BT 128            // map rows per CTA tile
#define KC 32             // k-elems per chunk
#define NCHUNK (C / KC)   // 4
#define PB 80             // smem row pitch in BYTES (40 bf16) — LDSM conflict-free
#define ARR_SZ (BT * PB)  // 10240 B per operand array
#define A_STAGE (2 * ARR_SZ)    // Ahi+Alo = 20480 B
#define B_STAGE (2 * ARR_SZ)    // Bhi+Blo = 20480 B
#define BREG (3 * A_STAGE)      // B region starts after 3 A stages = 61440
#define DYN_SMEM (3 * A_STAGE + 2 * B_STAGE)   // 102400 B
#define WCHUNK_B ARR_SZ         // one weight chunk image = 10240 B

// ---- scratch (static device allocations; allowed) ----
__device__ __align__(16) float         g_acc[(size_t)N_PTS * C];
__device__ __align__(16) __nv_bfloat16 g_xhi[(size_t)N_PTS * C];
__device__ __align__(16) __nv_bfloat16 g_xlo[(size_t)N_PTS * C];
__device__ __align__(16) __nv_bfloat16 g_yhi[(size_t)N_PTS * C];
__device__ __align__(16) __nv_bfloat16 g_ylo[(size_t)N_PTS * C];
// weights pre-arranged as the exact smem tile image:
// [k][chunk][row 0..127][40 bf16 (80 B pitch, first 32 valid)]
__device__ __align__(16) __nv_bfloat16 g_wthi[(size_t)KNUM * NCHUNK * BT * (PB / 2)];
__device__ __align__(16) __nv_bfloat16 g_wtlo[(size_t)KNUM * NCHUNK * BT * (PB / 2)];
__device__ __align__(16) float g_sum[C];
__device__ __align__(16) float g_sq[C];

// ---------------------------------------------------------------------------
// helpers
// ---------------------------------------------------------------------------
__device__ __forceinline__ uint32_t smem_u32(const void* p)
{
    uint32_t a;
    asm("{ .reg .u64 t; cvta.to.shared.u64 t, %1; cvt.u32.u64 %0, t; }"
        : "=r"(a) : "l"(p));
    return a;
}

__device__ __forceinline__ void split_bf16(float v, __nv_bfloat16& h, __nv_bfloat16& l)
{
    h = __float2bfloat16_rn(v);
    l = __float2bfloat16_rn(v - __bfloat162float(h));
}

__device__ __forceinline__ void mma16816(float* c, const unsigned* a,
                                         unsigned b0, unsigned b1)
{
    asm volatile(
        "mma.sync.aligned.m16n8k16.row.col.f32.bf16.bf16.f32 "
        "{%0,%1,%2,%3}, {%4,%5,%6,%7}, {%8,%9}, {%0,%1,%2,%3};"
        : "+f"(c[0]), "+f"(c[1]), "+f"(c[2]), "+f"(c[3])
        : "r"(a[0]), "r"(a[1]), "r"(a[2]), "r"(a[3]), "r"(b0), "r"(b1));
}

__device__ __forceinline__ void ldsm_x4(unsigned* r, uint32_t addr)
{
    asm volatile("ldmatrix.sync.aligned.m8n8.x4.shared.b16 {%0,%1,%2,%3}, [%4];"
                 : "=r"(r[0]), "=r"(r[1]), "=r"(r[2]), "=r"(r[3]) : "r"(addr));
}

#define CP_ASYNC16(dst, src) \
    asm volatile("cp.async.cg.shared.global [%0], [%1], 16;" :: "r"(dst), "l"(src))
#define CP_COMMIT() asm volatile("cp.async.commit_group;" ::: "memory")

__device__ __forceinline__ void bulk_copy(uint32_t dst, const void* src,
                                          uint32_t bytes, uint32_t mbar)
{
    asm volatile(
        "cp.async.bulk.shared::cta.global.mbarrier::complete_tx::bytes "
        "[%0], [%1], %2, [%3];"
        :: "r"(dst), "l"(src), "r"(bytes), "r"(mbar) : "memory");
}

__device__ __forceinline__ void mbar_expect_tx(uint32_t mbar, uint32_t bytes)
{
    asm volatile("mbarrier.arrive.expect_tx.shared.b64 _, [%0], %1;"
                 :: "r"(mbar), "r"(bytes) : "memory");
}

__device__ __forceinline__ void mbar_wait(uint32_t mbar, uint32_t parity)
{
    uint32_t done;
    asm volatile(
        "{\n\t.reg .pred p;\n\t"
        "mbarrier.try_wait.parity.acquire.cta.shared::cta.b64 p, [%1], %2;\n\t"
        "selp.b32 %0, 1, 0, p;\n\t}"
        : "=r"(done) : "r"(mbar), "r"(parity) : "memory");
    if (!done) {
        asm volatile(
            "{\n\t.reg .pred P1;\n\t"
            "WL_%=:\n\t"
            "mbarrier.try_wait.parity.acquire.cta.shared::cta.b64 P1, [%0], %1, 0x989680;\n\t"
            "@P1 bra.uni WD_%=;\n\t"
            "bra.uni WL_%=;\n\t"
            "WD_%=:\n\t}"
            :: "r"(mbar), "r"(parity) : "memory");
    }
}

__device__ __forceinline__ float elu_f(float x)
{
    return x > 0.0f ? x : expm1f(x);
}

// ---------------------------------------------------------------------------
// Prepack kernels
// ---------------------------------------------------------------------------
__global__ __launch_bounds__(256)
void prepack_x_kernel(const float* __restrict__ src,
                      __nv_bfloat16* __restrict__ hi,
                      __nv_bfloat16* __restrict__ lo,
                      float* __restrict__ acc_zero)
{
    size_t i = (size_t)blockIdx.x * 256 + threadIdx.x;
    float4 v = ((const float4*)src)[i];
    __nv_bfloat16 h0, h1, h2, h3, l0, l1, l2, l3;
    split_bf16(v.x, h0, l0); split_bf16(v.y, h1, l1);
    split_bf16(v.z, h2, l2); split_bf16(v.w, h3, l3);
    ((__nv_bfloat162*)hi)[i * 2 + 0] = __nv_bfloat162(h0, h1);
    ((__nv_bfloat162*)hi)[i * 2 + 1] = __nv_bfloat162(h2, h3);
    ((__nv_bfloat162*)lo)[i * 2 + 0] = __nv_bfloat162(l0, l1);
    ((__nv_bfloat162*)lo)[i * 2 + 1] = __nv_bfloat162(l2, l3);
    ((float4*)acc_zero)[i] = make_float4(0.f, 0.f, 0.f, 0.f);   // layer-1 acc zero
}

// W[k][cin][n] fp32 -> smem-image layout: [k][chunk=cin>>5][n][cin&31] @ 80B pitch
// Block 0 also zeroes the BN stats for the UPCOMING layer. This kernel is
// stream-ordered after the previous layer's apply (which READS the stats),
// so the zeroing is race-free — unlike R13 where apply both read and zeroed.
__global__ __launch_bounds__(256)
void prepack_w_kernel(const float* __restrict__ W)
{
    int k = blockIdx.x;
    if (k == 0 && threadIdx.x < C) {
        g_sum[threadIdx.x] = 0.0f;
        g_sq[threadIdx.x]  = 0.0f;
    }
    const float* Wk = W + (size_t)k * C * C;
    for (int idx = threadIdx.x; idx < C * C; idx += 256) {
        int n   = idx & (C - 1);
        int cin = idx >> 7;
        float v = Wk[(size_t)cin * C + n];
        __nv_bfloat16 h, l;
        split_bf16(v, h, l);
        int ch  = cin >> 5;
        int col = cin & 31;
        size_t off = ((size_t)(k * NCHUNK + ch) * BT + n) * (PB / 2) + col;
        g_wthi[off] = h;
        g_wtlo[off] = l;
    }
}

// ---------------------------------------------------------------------------
// Sparse conv: mma.sync + ldmatrix; A via 3-stage cp.async, B via 2-stage bulk.
// CTA = 128 map rows x 128 out channels; 8 warps, warp tile 32M x 64N.
// ONE barrier per chunk; scatter indices preloaded into smem.
// ---------------------------------------------------------------------------
__global__ __launch_bounds__(256, 2)
void spconv_mma_kernel(const __nv_bfloat16* __restrict__ xhi,
                       const __nv_bfloat16* __restrict__ xlo,
                       const int* __restrict__ map_in,
                       const int* __restrict__ map_out,
                       float* __restrict__ acc_out)
{
    extern __shared__ __align__(16) char dynsmem[];
    __shared__ int rowidx[BT];
    __shared__ int outidx[BT];
    __shared__ __align__(8) uint64_t s_mbar[2];

    const int k    = blockIdx.y;
    const int m0   = blockIdx.x * BT;
    const int tid  = threadIdx.x;
    const int warp = tid >> 5;
    const int lane = tid & 31;
    const int wm   = warp & 3;            // M warp: 32 rows
    const int wn   = warp >> 2;           // N warp: 64 cols

    const int* mi = map_in  + (size_t)k * M_MAP + m0;
    const int* mo = map_out + (size_t)k * M_MAP + m0;
    const char* wbh = (const char*)g_wthi + (size_t)k * NCHUNK * WCHUNK_B;
    const char* wbl = (const char*)g_wtlo + (size_t)k * NCHUNK * WCHUNK_B;

    const uint32_t sbase = smem_u32(dynsmem);
    const uint32_t mb0   = smem_u32(&s_mbar[0]);
    const uint32_t mb1   = smem_u32(&s_mbar[1]);

    if (tid < BT) {
        rowidx[tid] = mi[tid];
        outidx[tid] = mo[tid];
    }
    if (tid == 0) {
        asm volatile("mbarrier.init.shared.b64 [%0], 1;" :: "r"(mb0) : "memory");
        asm volatile("mbarrier.init.shared.b64 [%0], 1;" :: "r"(mb1) : "memory");
        asm volatile("fence.proxy.async.shared::cta;" ::: "memory");
    }
    __syncthreads();

    // --- per-thread cp.async source/dest for A (4 transfers per chunk) ---
    const __nv_bfloat16* srcs[4];
    uint32_t doffs[4];
    #pragma unroll
    for (int it = 0; it < 4; it++) {
        int idx = tid + it * 256;          // 0..1023
        int a   = idx >> 9;                // 0: hi, 1: lo
        int rem = idx & 511;
        int row = rem >> 2;
        int q   = rem & 3;
        const __nv_bfloat16* s = (a == 0 ? xhi : xlo) + (size_t)rowidx[row] * C;
        srcs[it]  = s + q * 8;
        doffs[it] = (uint32_t)(a * ARR_SZ + row * PB + q * 16);
    }

    // --- ldmatrix per-thread offsets (within a stage) ---
    const int mat = lane >> 3;
    const int mi8 = lane & 7;
    const uint32_t aRow  = (uint32_t)(wm * 32 + (mat & 1) * 8 + mi8);
    const uint32_t aColB = (uint32_t)((mat >> 1) * 8) * 2;
    uint32_t aOff[2];
    aOff[0] = aRow * PB + aColB;
    aOff[1] = (aRow + 16) * PB + aColB;
    const uint32_t bRow  = (uint32_t)(wn * 64 + (mat >> 1) * 8 + mi8);
    const uint32_t bColB = (uint32_t)((mat & 1) * 8) * 2;
    uint32_t bOff[4];
    #pragma unroll
    for (int p = 0; p < 4; p++)
        bOff[p] = (bRow + p * 16) * PB + bColB;

    float acc[2][8][4];
    #pragma unroll
    for (int i = 0; i < 2; i++)
        #pragma unroll
        for (int j = 0; j < 8; j++)
            #pragma unroll
            for (int t = 0; t < 4; t++) acc[i][j][t] = 0.0f;

    // ---- preload: A chunks 0,1 (stages 0,1) and B chunk 0 (stage 0) ----
    #pragma unroll
    for (int pre = 0; pre < 2; pre++) {
        const uint32_t st = (uint32_t)(pre * A_STAGE);
        const int coff = pre * KC;
        #pragma unroll
        for (int it = 0; it < 4; it++)
            CP_ASYNC16(sbase + st + doffs[it], srcs[it] + coff);
        CP_COMMIT();
    }
    if (tid == 0) {
        mbar_expect_tx(mb0, 2 * WCHUNK_B);
        bulk_copy(sbase + BREG, wbh, WCHUNK_B, mb0);
        bulk_copy(sbase + BREG + ARR_SZ, wbl, WCHUNK_B, mb0);
    }

    #pragma unroll
    for (int ch = 0; ch < NCHUNK; ch++) {
        // ---- wait for chunk ch (A groups FIFO; B via mbarrier) ----
        if (ch < NCHUNK - 1) asm volatile("cp.async.wait_group 1;" ::: "memory");
        else                 asm volatile("cp.async.wait_group 0;" ::: "memory");
        mbar_wait((ch & 1) ? mb1 : mb0, (uint32_t)((ch >> 1) & 1));
        __syncthreads();   // ONLY barrier this chunk

        // ---- issue next-chunk copies (safe: stage readers all past barrier) ----
        if (ch + 2 < NCHUNK) {
            const uint32_t st = (uint32_t)(((ch + 2) % 3) * A_STAGE);
            const int coff = (ch + 2) * KC;
            #pragma unroll
            for (int it = 0; it < 4; it++)
                CP_ASYNC16(sbase + st + doffs[it], srcs[it] + coff);
            CP_COMMIT();
        }
        if (ch + 1 < NCHUNK && tid == 0) {
            const uint32_t nmb = ((ch + 1) & 1) ? mb1 : mb0;
            const uint32_t dst = sbase + BREG + (uint32_t)(((ch + 1) & 1) * B_STAGE);
            mbar_expect_tx(nmb, 2 * WCHUNK_B);
            bulk_copy(dst, wbh + (size_t)(ch + 1) * WCHUNK_B, WCHUNK_B, nmb);
            bulk_copy(dst + ARR_SZ, wbl + (size_t)(ch + 1) * WCHUNK_B, WCHUNK_B, nmb);
        }

        const uint32_t stA = sbase + (uint32_t)((ch % 3) * A_STAGE);
        const uint32_t stB = sbase + BREG + (uint32_t)((ch % 2) * B_STAGE);

        #pragma unroll
        for (int ks = 0; ks < KC / 16; ks++) {
            const uint32_t kb = (uint32_t)(ks * 32);
            unsigned ah[2][4], al[2][4];
            ldsm_x4(ah[0], stA + aOff[0] + kb);
            ldsm_x4(ah[1], stA + aOff[1] + kb);
            ldsm_x4(al[0], stA + ARR_SZ + aOff[0] + kb);
            ldsm_x4(al[1], stA + ARR_SZ + aOff[1] + kb);
            #pragma unroll
            for (int p = 0; p < 4; p++) {
                unsigned bh[4], bl[4];
                ldsm_x4(bh, stB + bOff[p] + kb);
                ldsm_x4(bl, stB + ARR_SZ + bOff[p] + kb);
                #pragma unroll
                for (int ns = 0; ns < 2; ns++) {
                    const int nb = p * 2 + ns;
                    #pragma unroll
                    for (int mb = 0; mb < 2; mb++) {
                        mma16816(acc[mb][nb], ah[mb], bh[ns * 2], bh[ns * 2 + 1]);
                        mma16816(acc[mb][nb], ah[mb], bl[ns * 2], bl[ns * 2 + 1]);
                        mma16816(acc[mb][nb], al[mb], bh[ns * 2], bh[ns * 2 + 1]);
                    }
                }
            }
        }
    }

    // ---- epilogue: shfl-swap fragments into 4-col runs, scatter v4 reds ----
    {
        const int g    = lane >> 2;
        const int tig  = lane & 3;
        const int oddp = tig & 1;
        #pragma unroll
        for (int mb = 0; mb < 2; mb++) {
            const int r    = wm * 32 + mb * 16 + g + oddp * 8;
            const int orow = outidx[r];
            float* dst = acc_out + (size_t)orow * C + wn * 64 + (tig >> 1) * 4;
            #pragma unroll
            for (int nb = 0; nb < 8; nb++) {
                float s0 = oddp ? acc[mb][nb][0] : acc[mb][nb][2];
                float s1 = oddp ? acc[mb][nb][1] : acc[mb][nb][3];
                float r0 = __shfl_xor_sync(0xFFFFFFFFu, s0, 1);
                float r1 = __shfl_xor_sync(0xFFFFFFFFu, s1, 1);
                float v0 = oddp ? r0 : acc[mb][nb][0];
                float v1 = oddp ? r1 : acc[mb][nb][1];
                float v2 = oddp ? acc[mb][nb][2] : r0;
                float v3 = oddp ? acc[mb][nb][3] : r1;
                asm volatile("red.global.v4.f32.add [%0], {%1, %2, %3, %4};"
                             :: "l"(dst + nb * 8), "f"(v0), "f"(v1), "f"(v2), "f"(v3)
                             : "memory");
            }
        }
    }
}

// ---------------------------------------------------------------------------
// BN stats
// ---------------------------------------------------------------------------
__global__ __launch_bounds__(256)
void bn_stats_kernel(const float* __restrict__ a)
{
    __shared__ float4 ss[256];
    __shared__ float4 qq[256];
    const int tid = threadIdx.x;
    const int c4  = tid & 31;
    const int ro  = tid >> 5;

    float4 s = make_float4(0.f, 0.f, 0.f, 0.f);
    float4 p = make_float4(0.f, 0.f, 0.f, 0.f);
    for (int r = blockIdx.x * 8 + ro; r < N_PTS; r += gridDim.x * 8) {
        float4 v = ((const float4*)a)[(size_t)r * 32 + c4];
        s.x += v.x; s.y += v.y; s.z += v.z; s.w += v.w;
        p.x += v.x * v.x; p.y += v.y * v.y; p.z += v.z * v.z; p.w += v.w * v.w;
    }
    ss[tid] = s;
    qq[tid] = p;
    __syncthreads();
    if (tid < 32) {
        float4 S = ss[tid], Q = qq[tid];
        #pragma unroll
        for (int j = 1; j < 8; j++) {
            float4 s2 = ss[tid + j * 32], q2 = qq[tid + j * 32];
            S.x += s2.x; S.y += s2.y; S.z += s2.z; S.w += s2.w;
            Q.x += q2.x; Q.y += q2.y; Q.z += q2.z; Q.w += q2.w;
        }
        atomicAdd(&g_sum[tid * 4 + 0], S.x);
        atomicAdd(&g_sum[tid * 4 + 1], S.y);
        atomicAdd(&g_sum[tid * 4 + 2], S.z);
        atomicAdd(&g_sum[tid * 4 + 3], S.w);
        atomicAdd(&g_sq[tid * 4 + 0], Q.x);
        atomicAdd(&g_sq[tid * 4 + 1], Q.y);
        atomicAdd(&g_sq[tid * 4 + 2], Q.z);
        atomicAdd(&g_sq[tid * 4 + 3], Q.w);
    }
}

// ---------------------------------------------------------------------------
// Apply kernels (finalize folded in: per-block scale/shift from g_sum/g_sq;
// these kernels ONLY READ the stats — zeroing happens in prepack_w)
// ---------------------------------------------------------------------------
__global__ __launch_bounds__(256)
void apply_bn_elu_split_kernel(float* __restrict__ a,
                               const float* __restrict__ gamma,
                               const float* __restrict__ beta,
                               __nv_bfloat16* __restrict__ yh,
                               __nv_bfloat16* __restrict__ yl)
{
    __shared__ float s_scale[C];
    __shared__ float s_shift[C];
    const int tid = threadIdx.x;
    if (tid < C) {
        float m  = g_sum[tid] * (1.0f / N_PTS);
        float v  = g_sq[tid] * (1.0f / N_PTS) - m * m;
        float is = rsqrtf(v + EPS);
        float sc = is * gamma[tid];
        s_scale[tid] = sc;
        s_shift[tid] = beta[tid] - m * sc;
    }
    __syncthreads();
    size_t idx = (size_t)blockIdx.x * 256 + tid;
    int c4 = (int)(idx & 31);
    float4 v  = ((const float4*)a)[idx];
    float4 sc = ((const float4*)s_scale)[c4];
    float4 sh = ((const float4*)s_shift)[c4];
    ((float4*)a)[idx] = make_float4(0.f, 0.f, 0.f, 0.f);   // zero acc for layer 2
    float4 r;
    r.x = elu_f(fmaf(v.x, sc.x, sh.x));
    r.y = elu_f(fmaf(v.y, sc.y, sh.y));
    r.z = elu_f(fmaf(v.z, sc.z, sh.z));
    r.w = elu_f(fmaf(v.w, sc.w, sh.w));
    __nv_bfloat16 h0, h1, h2, h3, l0, l1, l2, l3;
    split_bf16(r.x, h0, l0); split_bf16(r.y, h1, l1);
    split_bf16(r.z, h2, l2); split_bf16(r.w, h3, l3);
    ((__nv_bfloat162*)yh)[idx * 2 + 0] = __nv_bfloat162(h0, h1);
    ((__nv_bfloat162*)yh)[idx * 2 + 1] = __nv_bfloat162(h2, h3);
    ((__nv_bfloat162*)yl)[idx * 2 + 0] = __nv_bfloat162(l0, l1);
    ((__nv_bfloat162*)yl)[idx * 2 + 1] = __nv_bfloat162(l2, l3);
}

__global__ __launch_bounds__(256)
void apply_bn_res_elu_kernel(const float* __restrict__ a,
                             const float* __restrict__ gamma,
                             const float* __restrict__ beta,
                             const float* __restrict__ resid,
                             float* __restrict__ o)
{
    __shared__ float s_scale[C];
    __shared__ float s_shift[C];
    const int tid = threadIdx.x;
    if (tid < C) {
        float m  = g_sum[tid] * (1.0f / N_PTS);
        float v  = g_sq[tid] * (1.0f / N_PTS) - m * m;
        float is = rsqrtf(v + EPS);
        float sc = is * gamma[tid];
        s_scale[tid] = sc;
        s_shift[tid] = beta[tid] - m * sc;
    }
    __syncthreads();
    size_t idx = (size_t)blockIdx.x * 256 + tid;
    int c4 = (int)(idx & 31);
    float4 v  = ((const float4*)a)[idx];
    float4 rs = ((const float4*)resid)[idx];
    float4 sc = ((const float4*)s_scale)[c4];
    float4 sh = ((const float4*)s_shift)[c4];
    float4 r;
    r.x = elu_f(fmaf(v.x, sc.x, sh.x) + rs.x);
    r.y = elu_f(fmaf(v.y, sc.y, sh.y) + rs.y);
    r.z = elu_f(fmaf(v.z, sc.z, sh.z) + rs.z);
    r.w = elu_f(fmaf(v.w, sc.w, sh.w) + rs.w);
    ((float4*)o)[idx] = r;
}

// ---------------------------------------------------------------------------
// Launch
// ---------------------------------------------------------------------------
extern "C" void kernel_launch(void* const* d_in, const int* in_sizes, int n_in,
                              void* d_out, int out_size)
{
    const float* x       = (const float*)d_in[0];
    const float* W1      = (const float*)d_in[1];
    const float* gamma1  = (const float*)d_in[2];
    const float* beta1   = (const float*)d_in[3];
    const float* W2      = (const float*)d_in[4];
    const float* gamma2  = (const float*)d_in[5];
    const float* beta2   = (const float*)d_in[6];
    const int*   map1_in  = (const int*)d_in[7];
    const int*   map1_out = (const int*)d_in[8];
    const int*   map2_in  = (const int*)d_in[9];
    const int*   map2_out = (const int*)d_in[10];
    float* out = (float*)d_out;

    void *accPtr, *xhiPtr, *xloPtr, *yhiPtr, *yloPtr;
    cudaGetSymbolAddress(&accPtr, g_acc);
    cudaGetSymbolAddress(&xhiPtr, g_xhi);
    cudaGetSymbolAddress(&xloPtr, g_xlo);
    cudaGetSymbolAddress(&yhiPtr, g_yhi);
    cudaGetSymbolAddress(&yloPtr, g_ylo);

    cudaFuncSetAttribute(spconv_mma_kernel,
                         cudaFuncAttributeMaxDynamicSharedMemorySize, DYN_SMEM);

    const dim3 convGrid(M_MAP / BT, KNUM);
    const int  elem4  = (N_PTS * C) / 4;
    const int  ewGrid = elem4 / 256;

    // ---- prepack (prepack_w block 0 zeroes layer-1 stats) ----
    prepack_x_kernel<<<ewGrid, 256>>>(x, (__nv_bfloat16*)xhiPtr,
                                      (__nv_bfloat16*)xloPtr, (float*)accPtr);
    prepack_w_kernel<<<KNUM, 256>>>(W1);

    // ---- layer 1 ----
    spconv_mma_kernel<<<convGrid, 256, DYN_SMEM>>>(
        (const __nv_bfloat16*)xhiPtr, (const __nv_bfloat16*)xloPtr,
        map1_in, map1_out, (float*)accPtr);
    bn_stats_kernel<<<1024, 256>>>((const float*)accPtr);
    apply_bn_elu_split_kernel<<<ewGrid, 256>>>(
        (float*)accPtr, gamma1, beta1,
        (__nv_bfloat16*)yhiPtr, (__nv_bfloat16*)yloPtr);

    // ---- layer 2 (prepack_w block 0 zeroes layer-2 stats AFTER apply read them) ----
    prepack_w_kernel<<<KNUM, 256>>>(W2);
    spconv_mma_kernel<<<convGrid, 256, DYN_SMEM>>>(
        (const __nv_bfloat16*)yhiPtr, (const __nv_bfloat16*)yloPtr,
        map2_in, map2_out, (float*)accPtr);
    bn_stats_kernel<<<1024, 256>>>((const float*)accPtr);
    apply_bn_res_elu_kernel<<<ewGrid, 256>>>(
        (const float*)accPtr, gamma2, beta2, x, out);
}

// round 15
// speedup vs baseline: 2.5443x; 1.0225x over previous
#include <cuda_runtime.h>
#include <cuda_bf16.h>
#include <math.h>
#include <stdint.h>

#define N_PTS 131072
#define C 128
#define KNUM 27
#define M_MAP 65536
#define EPS 1e-5f

#define BT 128            // map rows per CTA tile
#define KC 32             // k-elems per chunk
#define NCHUNK (C / KC)   // 4
#define PB 80             // smem row pitch in BYTES (40 bf16) — LDSM conflict-free
#define ARR_SZ (BT * PB)  // 10240 B per operand array
#define A_STAGE (2 * ARR_SZ)    // Ahi+Alo = 20480 B
#define B_STAGE (2 * ARR_SZ)    // Bhi+Blo = 20480 B
#define BREG (3 * A_STAGE)      // B region starts after 3 A stages = 61440
#define DYN_SMEM (3 * A_STAGE + 2 * B_STAGE)   // 102400 B
#define WCHUNK_B ARR_SZ         // one weight chunk image = 10240 B
#define WLAYER_B ((size_t)KNUM * NCHUNK * WCHUNK_B)   // per-layer weight image bytes

// ---- scratch (static device allocations; allowed) ----
__device__ __align__(16) float         g_acc[(size_t)N_PTS * C];
__device__ __align__(16) __nv_bfloat16 g_xhi[(size_t)N_PTS * C];
__device__ __align__(16) __nv_bfloat16 g_xlo[(size_t)N_PTS * C];
__device__ __align__(16) __nv_bfloat16 g_yhi[(size_t)N_PTS * C];
__device__ __align__(16) __nv_bfloat16 g_ylo[(size_t)N_PTS * C];
// weight smem-images for BOTH layers: [layer][k][chunk][row][40 bf16 @80B pitch]
__device__ __align__(16) __nv_bfloat16 g_wthi[2 * (size_t)KNUM * NCHUNK * BT * (PB / 2)];
__device__ __align__(16) __nv_bfloat16 g_wtlo[2 * (size_t)KNUM * NCHUNK * BT * (PB / 2)];
__device__ __align__(16) float g_sum[C];
__device__ __align__(16) float g_sq[C];

// ---------------------------------------------------------------------------
// helpers
// ---------------------------------------------------------------------------
__device__ __forceinline__ uint32_t smem_u32(const void* p)
{
    uint32_t a;
    asm("{ .reg .u64 t; cvta.to.shared.u64 t, %1; cvt.u32.u64 %0, t; }"
        : "=r"(a) : "l"(p));
    return a;
}

__device__ __forceinline__ void split_bf16(float v, __nv_bfloat16& h, __nv_bfloat16& l)
{
    h = __float2bfloat16_rn(v);
    l = __float2bfloat16_rn(v - __bfloat162float(h));
}

__device__ __forceinline__ void mma16816(float* c, const unsigned* a,
                                         unsigned b0, unsigned b1)
{
    asm volatile(
        "mma.sync.aligned.m16n8k16.row.col.f32.bf16.bf16.f32 "
        "{%0,%1,%2,%3}, {%4,%5,%6,%7}, {%8,%9}, {%0,%1,%2,%3};"
        : "+f"(c[0]), "+f"(c[1]), "+f"(c[2]), "+f"(c[3])
        : "r"(a[0]), "r"(a[1]), "r"(a[2]), "r"(a[3]), "r"(b0), "r"(b1));
}

__device__ __forceinline__ void ldsm_x4(unsigned* r, uint32_t addr)
{
    asm volatile("ldmatrix.sync.aligned.m8n8.x4.shared.b16 {%0,%1,%2,%3}, [%4];"
                 : "=r"(r[0]), "=r"(r[1]), "=r"(r[2]), "=r"(r[3]) : "r"(addr));
}

#define CP_ASYNC16(dst, src) \
    asm volatile("cp.async.cg.shared.global [%0], [%1], 16;" :: "r"(dst), "l"(src))
#define CP_COMMIT() asm volatile("cp.async.commit_group;" ::: "memory")

__device__ __forceinline__ void bulk_copy(uint32_t dst, const void* src,
                                          uint32_t bytes, uint32_t mbar)
{
    asm volatile(
        "cp.async.bulk.shared::cta.global.mbarrier::complete_tx::bytes "
        "[%0], [%1], %2, [%3];"
        :: "r"(dst), "l"(src), "r"(bytes), "r"(mbar) : "memory");
}

__device__ __forceinline__ void mbar_expect_tx(uint32_t mbar, uint32_t bytes)
{
    asm volatile("mbarrier.arrive.expect_tx.shared.b64 _, [%0], %1;"
                 :: "r"(mbar), "r"(bytes) : "memory");
}

__device__ __forceinline__ void mbar_wait(uint32_t mbar, uint32_t parity)
{
    uint32_t done;
    asm volatile(
        "{\n\t.reg .pred p;\n\t"
        "mbarrier.try_wait.parity.acquire.cta.shared::cta.b64 p, [%1], %2;\n\t"
        "selp.b32 %0, 1, 0, p;\n\t}"
        : "=r"(done) : "r"(mbar), "r"(parity) : "memory");
    if (!done) {
        asm volatile(
            "{\n\t.reg .pred P1;\n\t"
            "WL_%=:\n\t"
            "mbarrier.try_wait.parity.acquire.cta.shared::cta.b64 P1, [%0], %1, 0x989680;\n\t"
            "@P1 bra.uni WD_%=;\n\t"
            "bra.uni WL_%=;\n\t"
            "WD_%=:\n\t}"
            :: "r"(mbar), "r"(parity) : "memory");
    }
}

__device__ __forceinline__ float elu_f(float x)
{
    return x > 0.0f ? x : expm1f(x);
}

// ---------------------------------------------------------------------------
// Prepack kernels
// ---------------------------------------------------------------------------
__global__ __launch_bounds__(256)
void prepack_x_kernel(const float* __restrict__ src,
                      __nv_bfloat16* __restrict__ hi,
                      __nv_bfloat16* __restrict__ lo,
                      float* __restrict__ acc_zero)
{
    size_t i = (size_t)blockIdx.x * 256 + threadIdx.x;
    float4 v = ((const float4*)src)[i];
    __nv_bfloat16 h0, h1, h2, h3, l0, l1, l2, l3;
    split_bf16(v.x, h0, l0); split_bf16(v.y, h1, l1);
    split_bf16(v.z, h2, l2); split_bf16(v.w, h3, l3);
    ((__nv_bfloat162*)hi)[i * 2 + 0] = __nv_bfloat162(h0, h1);
    ((__nv_bfloat162*)hi)[i * 2 + 1] = __nv_bfloat162(h2, h3);
    ((__nv_bfloat162*)lo)[i * 2 + 0] = __nv_bfloat162(l0, l1);
    ((__nv_bfloat162*)lo)[i * 2 + 1] = __nv_bfloat162(l2, l3);
    ((float4*)acc_zero)[i] = make_float4(0.f, 0.f, 0.f, 0.f);   // layer-1 acc zero
}

// Both layers in one launch: blocks 0..26 pack W1, 27..53 pack W2.
__global__ __launch_bounds__(256)
void prepack_w_kernel(const float* __restrict__ W1,
                      const float* __restrict__ W2)
{
    int b     = blockIdx.x;
    int layer = b >= KNUM ? 1 : 0;
    int k     = b - layer * KNUM;
    const float* Wk = (layer ? W2 : W1) + (size_t)k * C * C;
    __nv_bfloat16* oh = g_wthi + (size_t)layer * KNUM * NCHUNK * BT * (PB / 2);
    __nv_bfloat16* ol = g_wtlo + (size_t)layer * KNUM * NCHUNK * BT * (PB / 2);
    for (int idx = threadIdx.x; idx < C * C; idx += 256) {
        int n   = idx & (C - 1);
        int cin = idx >> 7;
        float v = Wk[(size_t)cin * C + n];
        __nv_bfloat16 h, l;
        split_bf16(v, h, l);
        int ch  = cin >> 5;
        int col = cin & 31;
        size_t off = ((size_t)(k * NCHUNK + ch) * BT + n) * (PB / 2) + col;
        oh[off] = h;
        ol[off] = l;
    }
}

// ---------------------------------------------------------------------------
// Sparse conv: mma.sync + ldmatrix; A via 3-stage cp.async, B via 2-stage bulk.
// CTA = 128 map rows x 128 out channels; 8 warps, warp tile 32M x 64N.
// ONE barrier per chunk. CTA(0,0) zeroes BN stats for the upcoming bn_stats —
// race-free: previous reader (apply) is stream-ordered before this kernel.
// ---------------------------------------------------------------------------
__global__ __launch_bounds__(256, 2)
void spconv_mma_kernel(const __nv_bfloat16* __restrict__ xhi,
                       const __nv_bfloat16* __restrict__ xlo,
                       const __nv_bfloat16* __restrict__ wt_hi,
                       const __nv_bfloat16* __restrict__ wt_lo,
                       const int* __restrict__ map_in,
                       const int* __restrict__ map_out,
                       float* __restrict__ acc_out)
{
    extern __shared__ __align__(16) char dynsmem[];
    __shared__ int rowidx[BT];
    __shared__ int outidx[BT];
    __shared__ __align__(8) uint64_t s_mbar[2];

    const int k    = blockIdx.y;
    const int m0   = blockIdx.x * BT;
    const int tid  = threadIdx.x;
    const int warp = tid >> 5;
    const int lane = tid & 31;
    const int wm   = warp & 3;            // M warp: 32 rows
    const int wn   = warp >> 2;           // N warp: 64 cols

    if (blockIdx.x == 0 && blockIdx.y == 0 && tid < C) {
        g_sum[tid] = 0.0f;
        g_sq[tid]  = 0.0f;
    }

    const int* mi = map_in  + (size_t)k * M_MAP + m0;
    const int* mo = map_out + (size_t)k * M_MAP + m0;
    const char* wbh = (const char*)wt_hi + (size_t)k * NCHUNK * WCHUNK_B;
    const char* wbl = (const char*)wt_lo + (size_t)k * NCHUNK * WCHUNK_B;

    const uint32_t sbase = smem_u32(dynsmem);
    const uint32_t mb0   = smem_u32(&s_mbar[0]);
    const uint32_t mb1   = smem_u32(&s_mbar[1]);

    if (tid < BT) {
        rowidx[tid] = mi[tid];
        outidx[tid] = mo[tid];
    }
    if (tid == 0) {
        asm volatile("mbarrier.init.shared.b64 [%0], 1;" :: "r"(mb0) : "memory");
        asm volatile("mbarrier.init.shared.b64 [%0], 1;" :: "r"(mb1) : "memory");
        asm volatile("fence.proxy.async.shared::cta;" ::: "memory");
    }
    __syncthreads();

    // --- per-thread cp.async source/dest for A (4 transfers per chunk) ---
    const __nv_bfloat16* srcs[4];
    uint32_t doffs[4];
    #pragma unroll
    for (int it = 0; it < 4; it++) {
        int idx = tid + it * 256;          // 0..1023
        int a   = idx >> 9;                // 0: hi, 1: lo
        int rem = idx & 511;
        int row = rem >> 2;
        int q   = rem & 3;
        const __nv_bfloat16* s = (a == 0 ? xhi : xlo) + (size_t)rowidx[row] * C;
        srcs[it]  = s + q * 8;
        doffs[it] = (uint32_t)(a * ARR_SZ + row * PB + q * 16);
    }

    // --- ldmatrix per-thread offsets (within a stage) ---
    const int mat = lane >> 3;
    const int mi8 = lane & 7;
    const uint32_t aRow  = (uint32_t)(wm * 32 + (mat & 1) * 8 + mi8);
    const uint32_t aColB = (uint32_t)((mat >> 1) * 8) * 2;
    uint32_t aOff[2];
    aOff[0] = aRow * PB + aColB;
    aOff[1] = (aRow + 16) * PB + aColB;
    const uint32_t bRow  = (uint32_t)(wn * 64 + (mat >> 1) * 8 + mi8);
    const uint32_t bColB = (uint32_t)((mat & 1) * 8) * 2;
    uint32_t bOff[4];
    #pragma unroll
    for (int p = 0; p < 4; p++)
        bOff[p] = (bRow + p * 16) * PB + bColB;

    float acc[2][8][4];
    #pragma unroll
    for (int i = 0; i < 2; i++)
        #pragma unroll
        for (int j = 0; j < 8; j++)
            #pragma unroll
            for (int t = 0; t < 4; t++) acc[i][j][t] = 0.0f;

    // ---- preload: A chunks 0,1 (stages 0,1) and B chunk 0 (stage 0) ----
    #pragma unroll
    for (int pre = 0; pre < 2; pre++) {
        const uint32_t st = (uint32_t)(pre * A_STAGE);
        const int coff = pre * KC;
        #pragma unroll
        for (int it = 0; it < 4; it++)
            CP_ASYNC16(sbase + st + doffs[it], srcs[it] + coff);
        CP_COMMIT();
    }
    if (tid == 0) {
        mbar_expect_tx(mb0, 2 * WCHUNK_B);
        bulk_copy(sbase + BREG, wbh, WCHUNK_B, mb0);
        bulk_copy(sbase + BREG + ARR_SZ, wbl, WCHUNK_B, mb0);
    }

    #pragma unroll
    for (int ch = 0; ch < NCHUNK; ch++) {
        // ---- wait for chunk ch (A groups FIFO; B via mbarrier) ----
        if (ch < NCHUNK - 1) asm volatile("cp.async.wait_group 1;" ::: "memory");
        else                 asm volatile("cp.async.wait_group 0;" ::: "memory");
        mbar_wait((ch & 1) ? mb1 : mb0, (uint32_t)((ch >> 1) & 1));
        __syncthreads();   // ONLY barrier this chunk

        // ---- issue next-chunk copies (safe: stage readers all past barrier) ----
        if (ch + 2 < NCHUNK) {
            const uint32_t st = (uint32_t)(((ch + 2) % 3) * A_STAGE);
            const int coff = (ch + 2) * KC;
            #pragma unroll
            for (int it = 0; it < 4; it++)
                CP_ASYNC16(sbase + st + doffs[it], srcs[it] + coff);
            CP_COMMIT();
        }
        if (ch + 1 < NCHUNK && tid == 0) {
            const uint32_t nmb = ((ch + 1) & 1) ? mb1 : mb0;
            const uint32_t dst = sbase + BREG + (uint32_t)(((ch + 1) & 1) * B_STAGE);
            mbar_expect_tx(nmb, 2 * WCHUNK_B);
            bulk_copy(dst, wbh + (size_t)(ch + 1) * WCHUNK_B, WCHUNK_B, nmb);
            bulk_copy(dst + ARR_SZ, wbl + (size_t)(ch + 1) * WCHUNK_B, WCHUNK_B, nmb);
        }

        const uint32_t stA = sbase + (uint32_t)((ch % 3) * A_STAGE);
        const uint32_t stB = sbase + BREG + (uint32_t)((ch % 2) * B_STAGE);

        #pragma unroll
        for (int ks = 0; ks < KC / 16; ks++) {
            const uint32_t kb = (uint32_t)(ks * 32);
            unsigned ah[2][4], al[2][4];
            ldsm_x4(ah[0], stA + aOff[0] + kb);
            ldsm_x4(ah[1], stA + aOff[1] + kb);
            ldsm_x4(al[0], stA + ARR_SZ + aOff[0] + kb);
            ldsm_x4(al[1], stA + ARR_SZ + aOff[1] + kb);
            #pragma unroll
            for (int p = 0; p < 4; p++) {
                unsigned bh[4], bl[4];
                ldsm_x4(bh, stB + bOff[p] + kb);
                ldsm_x4(bl, stB + ARR_SZ + bOff[p] + kb);
                #pragma unroll
                for (int ns = 0; ns < 2; ns++) {
                    const int nb = p * 2 + ns;
                    #pragma unroll
                    for (int mb = 0; mb < 2; mb++) {
                        mma16816(acc[mb][nb], ah[mb], bh[ns * 2], bh[ns * 2 + 1]);
                        mma16816(acc[mb][nb], ah[mb], bl[ns * 2], bl[ns * 2 + 1]);
                        mma16816(acc[mb][nb], al[mb], bh[ns * 2], bh[ns * 2 + 1]);
                    }
                }
            }
        }
    }

    // ---- epilogue: shfl-swap fragments into 4-col runs, scatter v4 reds ----
    {
        const int g    = lane >> 2;
        const int tig  = lane & 3;
        const int oddp = tig & 1;
        #pragma unroll
        for (int mb = 0; mb < 2; mb++) {
            const int r    = wm * 32 + mb * 16 + g + oddp * 8;
            const int orow = outidx[r];
            float* dst = acc_out + (size_t)orow * C + wn * 64 + (tig >> 1) * 4;
            #pragma unroll
            for (int nb = 0; nb < 8; nb++) {
                float s0 = oddp ? acc[mb][nb][0] : acc[mb][nb][2];
                float s1 = oddp ? acc[mb][nb][1] : acc[mb][nb][3];
                float r0 = __shfl_xor_sync(0xFFFFFFFFu, s0, 1);
                float r1 = __shfl_xor_sync(0xFFFFFFFFu, s1, 1);
                float v0 = oddp ? r0 : acc[mb][nb][0];
                float v1 = oddp ? r1 : acc[mb][nb][1];
                float v2 = oddp ? acc[mb][nb][2] : r0;
                float v3 = oddp ? acc[mb][nb][3] : r1;
                asm volatile("red.global.v4.f32.add [%0], {%1, %2, %3, %4};"
                             :: "l"(dst + nb * 8), "f"(v0), "f"(v1), "f"(v2), "f"(v3)
                             : "memory");
            }
        }
    }
}

// ---------------------------------------------------------------------------
// BN stats (2-way unrolled for MLP)
// ---------------------------------------------------------------------------
__global__ __launch_bounds__(256)
void bn_stats_kernel(const float* __restrict__ a)
{
    __shared__ float4 ss[256];
    __shared__ float4 qq[256];
    const int tid = threadIdx.x;
    const int c4  = tid & 31;
    const int ro  = tid >> 5;

    float4 s = make_float4(0.f, 0.f, 0.f, 0.f);
    float4 p = make_float4(0.f, 0.f, 0.f, 0.f);
    for (int r = blockIdx.x * 16 + ro; r < N_PTS; r += gridDim.x * 16) {
        float4 v0 = ((const float4*)a)[(size_t)r * 32 + c4];
        float4 v1 = ((const float4*)a)[(size_t)(r + 8) * 32 + c4];
        s.x += v0.x + v1.x; s.y += v0.y + v1.y;
        s.z += v0.z + v1.z; s.w += v0.w + v1.w;
        p.x += v0.x * v0.x + v1.x * v1.x;
        p.y += v0.y * v0.y + v1.y * v1.y;
        p.z += v0.z * v0.z + v1.z * v1.z;
        p.w += v0.w * v0.w + v1.w * v1.w;
    }
    ss[tid] = s;
    qq[tid] = p;
    __syncthreads();
    if (tid < 32) {
        float4 S = ss[tid], Q = qq[tid];
        #pragma unroll
        for (int j = 1; j < 8; j++) {
            float4 s2 = ss[tid + j * 32], q2 = qq[tid + j * 32];
            S.x += s2.x; S.y += s2.y; S.z += s2.z; S.w += s2.w;
            Q.x += q2.x; Q.y += q2.y; Q.z += q2.z; Q.w += q2.w;
        }
        atomicAdd(&g_sum[tid * 4 + 0], S.x);
        atomicAdd(&g_sum[tid * 4 + 1], S.y);
        atomicAdd(&g_sum[tid * 4 + 2], S.z);
        atomicAdd(&g_sum[tid * 4 + 3], S.w);
        atomicAdd(&g_sq[tid * 4 + 0], Q.x);
        atomicAdd(&g_sq[tid * 4 + 1], Q.y);
        atomicAdd(&g_sq[tid * 4 + 2], Q.z);
        atomicAdd(&g_sq[tid * 4 + 3], Q.w);
    }
}

// ---------------------------------------------------------------------------
// Apply kernels (finalize folded in; they ONLY READ the stats)
// ---------------------------------------------------------------------------
__global__ __launch_bounds__(256)
void apply_bn_elu_split_kernel(float* __restrict__ a,
                               const float* __restrict__ gamma,
                               const float* __restrict__ beta,
                               __nv_bfloat16* __restrict__ yh,
                               __nv_bfloat16* __restrict__ yl)
{
    __shared__ float s_scale[C];
    __shared__ float s_shift[C];
    const int tid = threadIdx.x;
    if (tid < C) {
        float m  = g_sum[tid] * (1.0f / N_PTS);
        float v  = g_sq[tid] * (1.0f / N_PTS) - m * m;
        float is = rsqrtf(v + EPS);
        float sc = is * gamma[tid];
        s_scale[tid] = sc;
        s_shift[tid] = beta[tid] - m * sc;
    }
    __syncthreads();
    size_t idx = (size_t)blockIdx.x * 256 + tid;
    int c4 = (int)(idx & 31);
    float4 v  = ((const float4*)a)[idx];
    float4 sc = ((const float4*)s_scale)[c4];
    float4 sh = ((const float4*)s_shift)[c4];
    ((float4*)a)[idx] = make_float4(0.f, 0.f, 0.f, 0.f);   // zero acc for layer 2
    float4 r;
    r.x = elu_f(fmaf(v.x, sc.x, sh.x));
    r.y = elu_f(fmaf(v.y, sc.y, sh.y));
    r.z = elu_f(fmaf(v.z, sc.z, sh.z));
    r.w = elu_f(fmaf(v.w, sc.w, sh.w));
    __nv_bfloat16 h0, h1, h2, h3, l0, l1, l2, l3;
    split_bf16(r.x, h0, l0); split_bf16(r.y, h1, l1);
    split_bf16(r.z, h2, l2); split_bf16(r.w, h3, l3);
    ((__nv_bfloat162*)yh)[idx * 2 + 0] = __nv_bfloat162(h0, h1);
    ((__nv_bfloat162*)yh)[idx * 2 + 1] = __nv_bfloat162(h2, h3);
    ((__nv_bfloat162*)yl)[idx * 2 + 0] = __nv_bfloat162(l0, l1);
    ((__nv_bfloat162*)yl)[idx * 2 + 1] = __nv_bfloat162(l2, l3);
}

__global__ __launch_bounds__(256)
void apply_bn_res_elu_kernel(const float* __restrict__ a,
                             const float* __restrict__ gamma,
                             const float* __restrict__ beta,
                             const float* __restrict__ resid,
                             float* __restrict__ o)
{
    __shared__ float s_scale[C];
    __shared__ float s_shift[C];
    const int tid = threadIdx.x;
    if (tid < C) {
        float m  = g_sum[tid] * (1.0f / N_PTS);
        float v  = g_sq[tid] * (1.0f / N_PTS) - m * m;
        float is = rsqrtf(v + EPS);
        float sc = is * gamma[tid];
        s_scale[tid] = sc;
        s_shift[tid] = beta[tid] - m * sc;
    }
    __syncthreads();
    size_t idx = (size_t)blockIdx.x * 256 + tid;
    int c4 = (int)(idx & 31);
    float4 v  = ((const float4*)a)[idx];
    float4 rs = ((const float4*)resid)[idx];
    float4 sc = ((const float4*)s_scale)[c4];
    float4 sh = ((const float4*)s_shift)[c4];
    float4 r;
    r.x = elu_f(fmaf(v.x, sc.x, sh.x) + rs.x);
    r.y = elu_f(fmaf(v.y, sc.y, sh.y) + rs.y);
    r.z = elu_f(fmaf(v.z, sc.z, sh.z) + rs.z);
    r.w = elu_f(fmaf(v.w, sc.w, sh.w) + rs.w);
    ((float4*)o)[idx] = r;
}

// ---------------------------------------------------------------------------
// Launch
// ---------------------------------------------------------------------------
extern "C" void kernel_launch(void* const* d_in, const int* in_sizes, int n_in,
                              void* d_out, int out_size)
{
    const float* x       = (const float*)d_in[0];
    const float* W1      = (const float*)d_in[1];
    const float* gamma1  = (const float*)d_in[2];
    const float* beta1   = (const float*)d_in[3];
    const float* W2      = (const float*)d_in[4];
    const float* gamma2  = (const float*)d_in[5];
    const float* beta2   = (const float*)d_in[6];
    const int*   map1_in  = (const int*)d_in[7];
    const int*   map1_out = (const int*)d_in[8];
    const int*   map2_in  = (const int*)d_in[9];
    const int*   map2_out = (const int*)d_in[10];
    float* out = (float*)d_out;

    void *accPtr, *xhiPtr, *xloPtr, *yhiPtr, *yloPtr, *whiPtr, *wloPtr;
    cudaGetSymbolAddress(&accPtr, g_acc);
    cudaGetSymbolAddress(&xhiPtr, g_xhi);
    cudaGetSymbolAddress(&xloPtr, g_xlo);
    cudaGetSymbolAddress(&yhiPtr, g_yhi);
    cudaGetSymbolAddress(&yloPtr, g_ylo);
    cudaGetSymbolAddress(&whiPtr, g_wthi);
    cudaGetSymbolAddress(&wloPtr, g_wtlo);

    const __nv_bfloat16* w1hi = (const __nv_bfloat16*)whiPtr;
    const __nv_bfloat16* w1lo = (const __nv_bfloat16*)wloPtr;
    const __nv_bfloat16* w2hi = (const __nv_bfloat16*)((const char*)whiPtr + WLAYER_B);
    const __nv_bfloat16* w2lo = (const __nv_bfloat16*)((const char*)wloPtr + WLAYER_B);

    cudaFuncSetAttribute(spconv_mma_kernel,
                         cudaFuncAttributeMaxDynamicSharedMemorySize, DYN_SMEM);

    const dim3 convGrid(M_MAP / BT, KNUM);
    const int  elem4  = (N_PTS * C) / 4;
    const int  ewGrid = elem4 / 256;

    // ---- prepack both layers' weights + x up front ----
    prepack_x_kernel<<<ewGrid, 256>>>(x, (__nv_bfloat16*)xhiPtr,
                                      (__nv_bfloat16*)xloPtr, (float*)accPtr);
    prepack_w_kernel<<<2 * KNUM, 256>>>(W1, W2);

    // ---- layer 1 (conv CTA(0,0) zeroes stats) ----
    spconv_mma_kernel<<<convGrid, 256, DYN_SMEM>>>(
        (const __nv_bfloat16*)xhiPtr, (const __nv_bfloat16*)xloPtr,
        w1hi, w1lo, map1_in, map1_out, (float*)accPtr);
    bn_stats_kernel<<<1024, 256>>>((const float*)accPtr);
    apply_bn_elu_split_kernel<<<ewGrid, 256>>>(
        (float*)accPtr, gamma1, beta1,
        (__nv_bfloat16*)yhiPtr, (__nv_bfloat16*)yloPtr);

    // ---- layer 2 (conv CTA(0,0) zeroes stats AFTER apply read them) ----
    spconv_mma_kernel<<<convGrid, 256, DYN_SMEM>>>(
        (const __nv_bfloat16*)yhiPtr, (const __nv_bfloat16*)yloPtr,
        w2hi, w2lo, map2_in, map2_out, (float*)accPtr);
    bn_stats_kernel<<<1024, 256>>>((const float*)accPtr);
    apply_bn_res_elu_kernel<<<ewGrid, 256>>>(
        (const float*)accPtr, gamma2, beta2, x, out);
}